// round 14
// baseline (speedup 1.0000x reference)
#include <cuda_runtime.h>
#include <cuda_bf16.h>

// DGCRM live path only (DGCN branch dead; GConv_RNN bug makes hops alpha*x):
//   Wz=F(W0)+F(W1), Wr=F(W2)+F(W3), Wh=F(W4)+F(W5),
//   F(Wi)=Wi[0:66]+0.05*(Wi[66:132]+Wi[132:198])
//   z=sig(inp@Wz+bz); r=sig(inp@Wr+br); hc=tanh([x,r*hid]@Wh+bh)
//   out=z*hid+(1-z)*hc.  Internal col order: 0..63 hid, 64..65 x.
//
// R2: f32x2 packed FMAs (rows paired), column-major input tile for LDS.64
// operand loads, MT=64 -> 256 CTAs for 2 CTAs/SM occupancy.

#define NROWS 16384
#define KDIM  66
#define MT    64
#define NBLK  (NROWS / MT)   // 256
#define MTP   66             // sInT row stride (floats), 264B: 8B-aligned, staggers banks

typedef unsigned long long u64;

__device__ float g_W[3 * KDIM * 64];   // [mat][c'][j], c' permuted (hid first)
__device__ float g_b[3 * 64];

__device__ __forceinline__ float sigmoidf_(float v) {
    return 1.0f / (1.0f + __expf(-v));
}
__device__ __forceinline__ float tanh_fast(float v) {
    // tanh(v) = 2*sigmoid(2v) - 1  (exact at 0, correct saturation)
    return fmaf(2.0f, 1.0f / (1.0f + __expf(-2.0f * v)), -1.0f);
}
__device__ __forceinline__ u64 fma2(u64 a, u64 b, u64 c) {
    u64 d; asm("fma.rn.f32x2 %0, %1, %2, %3;" : "=l"(d) : "l"(a), "l"(b), "l"(c));
    return d;
}
__device__ __forceinline__ u64 dup2(float x) {
    u64 d; unsigned xi = __float_as_uint(x);
    asm("mov.b64 %0, {%1, %1};" : "=l"(d) : "r"(xi));
    return d;
}
__device__ __forceinline__ float2 unpk(u64 v) {
    unsigned lo, hi;
    asm("mov.b64 {%0, %1}, %2;" : "=r"(lo), "=r"(hi) : "l"(v));
    return make_float2(__uint_as_float(lo), __uint_as_float(hi));
}

__global__ void fold_kernel(const float* __restrict__ rnn_W,
                            const float* __restrict__ rnn_b) {
    int idx = blockIdx.x * 256 + threadIdx.x;
    if (idx < 3 * KDIM * 64) {
        int j = idx & 63;
        int c = (idx >> 6) % KDIM;
        int m = idx / (KDIM * 64);
        int orig = (c < 64) ? (c + 2) : (c - 64);   // original concat order: x first
        float v = 0.0f;
        #pragma unroll
        for (int t = 0; t < 2; t++) {
            const float* Wi = rnn_W + (size_t)(2 * m + t) * 198 * 64;
            v += Wi[orig * 64 + j]
               + 0.05f * (Wi[(66 + orig) * 64 + j] + Wi[(132 + orig) * 64 + j]);
        }
        g_W[idx] = v;
    }
    if (blockIdx.x == 0 && threadIdx.x < 3 * 64) {
        int m = threadIdx.x >> 6, j = threadIdx.x & 63;
        g_b[threadIdx.x] = rnn_b[(2 * m) * 64 + j] + rnn_b[(2 * m + 1) * 64 + j];
    }
}

// smem (floats): sInT[66][66] col-major input; sW[66][128]; sZ[64][65]; sB[192]
#define S_IN  0
#define S_W   (KDIM * MTP)                 // 4356
#define S_Z   (S_W + KDIM * 128)           // 12804
#define S_B   (S_Z + 64 * 65)              // 16964
#define SMEM_FLOATS (S_B + 192)            // 17156 floats = 68624 B

__global__ __launch_bounds__(256)
void dgcrm_main(const float* __restrict__ x,
                const float* __restrict__ hidden,
                float* __restrict__ out) {
    extern __shared__ float sm[];
    float* sInT = sm + S_IN;
    float* sW   = sm + S_W;
    float* sZ   = sm + S_Z;
    float* sB   = sm + S_B;

    const int tid  = threadIdx.x;
    const int row0 = blockIdx.x * MT;

    // ---- prologue: stage inputs (transposed) + zr weights ----
    for (int i = tid; i < MT * 16; i += 256) {            // hidden -> sInT[c][m]
        int m = i >> 4, q = i & 15;
        float4 v = reinterpret_cast<const float4*>(hidden)[(size_t)(row0 + m) * 16 + q];
        sInT[(4 * q + 0) * MTP + m] = v.x;
        sInT[(4 * q + 1) * MTP + m] = v.y;
        sInT[(4 * q + 2) * MTP + m] = v.z;
        sInT[(4 * q + 3) * MTP + m] = v.w;
    }
    for (int i = tid; i < MT * 2; i += 256) {             // x -> sInT[64|65][m]
        int m = i >> 1, c = i & 1;
        sInT[(64 + c) * MTP + m] = x[(size_t)(row0 + m) * 2 + c];
    }
    for (int i = tid; i < KDIM * 32; i += 256) {          // sW[c][0..127] = [Wz|Wr]
        int c = i >> 5, q = i & 31;
        float4 v = (q < 16)
            ? reinterpret_cast<const float4*>(g_W)[(0 * KDIM + c) * 16 + q]
            : reinterpret_cast<const float4*>(g_W)[(1 * KDIM + c) * 16 + (q - 16)];
        *reinterpret_cast<float4*>(&sW[c * 128 + q * 4]) = v;
    }
    if (tid < 192) sB[tid] = g_b[tid];
    __syncthreads();

    const int tx = tid & 31, ty = tid >> 5;
    const int m0 = ty * 8;          // 8 rows (4 packed pairs)
    const int n1 = tx * 4;          // pass1: 4 cols of 128

    // ---- pass 1: [64x66] @ [66x128] -> z|r pre-activations (f32x2) ----
    u64 acc[4][4];
    #pragma unroll
    for (int p = 0; p < 4; p++)
        #pragma unroll
        for (int j = 0; j < 4; j++) acc[p][j] = 0ull;

    #pragma unroll 2
    for (int c = 0; c < KDIM; c++) {
        const float* aP = sInT + c * MTP + m0;
        u64 a0 = *reinterpret_cast<const u64*>(aP + 0);
        u64 a1 = *reinterpret_cast<const u64*>(aP + 2);
        u64 a2 = *reinterpret_cast<const u64*>(aP + 4);
        u64 a3 = *reinterpret_cast<const u64*>(aP + 6);
        float4 b4 = *reinterpret_cast<const float4*>(sW + c * 128 + n1);
        u64 b0 = dup2(b4.x), b1 = dup2(b4.y), b2 = dup2(b4.z), b3 = dup2(b4.w);
        acc[0][0] = fma2(a0, b0, acc[0][0]); acc[0][1] = fma2(a0, b1, acc[0][1]);
        acc[0][2] = fma2(a0, b2, acc[0][2]); acc[0][3] = fma2(a0, b3, acc[0][3]);
        acc[1][0] = fma2(a1, b0, acc[1][0]); acc[1][1] = fma2(a1, b1, acc[1][1]);
        acc[1][2] = fma2(a1, b2, acc[1][2]); acc[1][3] = fma2(a1, b3, acc[1][3]);
        acc[2][0] = fma2(a2, b0, acc[2][0]); acc[2][1] = fma2(a2, b1, acc[2][1]);
        acc[2][2] = fma2(a2, b2, acc[2][2]); acc[2][3] = fma2(a2, b3, acc[2][3]);
        acc[3][0] = fma2(a3, b0, acc[3][0]); acc[3][1] = fma2(a3, b1, acc[3][1]);
        acc[3][2] = fma2(a3, b2, acc[3][2]); acc[3][3] = fma2(a3, b3, acc[3][3]);
    }
    __syncthreads();   // all reads of sInT/sW done before overwrite

    // ---- epilogue 1: z -> sZ ; r -> sInT (in place r*hid) ----
    if (n1 < 64) {
        #pragma unroll
        for (int p = 0; p < 4; p++) {
            int r = m0 + 2 * p;
            #pragma unroll
            for (int j = 0; j < 4; j++) {
                int col = n1 + j;
                float2 v = unpk(acc[p][j]);
                sZ[r * 65 + col]       = sigmoidf_(v.x + sB[col]);
                sZ[(r + 1) * 65 + col] = sigmoidf_(v.y + sB[col]);
            }
        }
    } else {
        #pragma unroll
        for (int p = 0; p < 4; p++) {
            int r = m0 + 2 * p;
            #pragma unroll
            for (int j = 0; j < 4; j++) {
                int col = n1 - 64 + j;
                float2 v = unpk(acc[p][j]);
                float* q = sInT + col * MTP + r;     // unique writer per element
                q[0] *= sigmoidf_(v.x + sB[64 + col]);
                q[1] *= sigmoidf_(v.y + sB[64 + col]);
            }
        }
    }
    // overwrite sW cols 0..63 with Wh
    for (int i = tid; i < KDIM * 16; i += 256) {
        int c = i >> 4, q = i & 15;
        *reinterpret_cast<float4*>(&sW[c * 128 + q * 4]) =
            reinterpret_cast<const float4*>(g_W)[(2 * KDIM + c) * 16 + q];
    }
    __syncthreads();

    // ---- pass 2: [64x66](cand) @ [66x64] -> hc pre-activations ----
    const int n2 = tx * 2;
    u64 acc2[4][2];
    #pragma unroll
    for (int p = 0; p < 4; p++) { acc2[p][0] = 0ull; acc2[p][1] = 0ull; }

    #pragma unroll 2
    for (int c = 0; c < KDIM; c++) {
        const float* aP = sInT + c * MTP + m0;
        u64 a0 = *reinterpret_cast<const u64*>(aP + 0);
        u64 a1 = *reinterpret_cast<const u64*>(aP + 2);
        u64 a2 = *reinterpret_cast<const u64*>(aP + 4);
        u64 a3 = *reinterpret_cast<const u64*>(aP + 6);
        float2 b2v = *reinterpret_cast<const float2*>(sW + c * 128 + n2);
        u64 b0 = dup2(b2v.x), b1 = dup2(b2v.y);
        acc2[0][0] = fma2(a0, b0, acc2[0][0]); acc2[0][1] = fma2(a0, b1, acc2[0][1]);
        acc2[1][0] = fma2(a1, b0, acc2[1][0]); acc2[1][1] = fma2(a1, b1, acc2[1][1]);
        acc2[2][0] = fma2(a2, b0, acc2[2][0]); acc2[2][1] = fma2(a2, b1, acc2[2][1]);
        acc2[3][0] = fma2(a3, b0, acc2[3][0]); acc2[3][1] = fma2(a3, b1, acc2[3][1]);
    }

    // ---- epilogue 2: out = z*hid + (1-z)*tanh(hc) ----
    #pragma unroll
    for (int p = 0; p < 4; p++) {
        int r = m0 + 2 * p;
        float2 v0 = unpk(acc2[p][0]);   // col n2,   rows r / r+1
        float2 v1 = unpk(acc2[p][1]);   // col n2+1, rows r / r+1
        float bh0 = sB[128 + n2], bh1 = sB[128 + n2 + 1];
        // row r
        {
            float hc0 = tanh_fast(v0.x + bh0);
            float hc1 = tanh_fast(v1.x + bh1);
            float z0 = sZ[r * 65 + n2], z1 = sZ[r * 65 + n2 + 1];
            float2 hv = *reinterpret_cast<const float2*>(&hidden[(size_t)(row0 + r) * 64 + n2]);
            float2 o;
            o.x = z0 * hv.x + (1.0f - z0) * hc0;
            o.y = z1 * hv.y + (1.0f - z1) * hc1;
            *reinterpret_cast<float2*>(&out[(size_t)(row0 + r) * 64 + n2]) = o;
        }
        // row r+1
        {
            float hc0 = tanh_fast(v0.y + bh0);
            float hc1 = tanh_fast(v1.y + bh1);
            float z0 = sZ[(r + 1) * 65 + n2], z1 = sZ[(r + 1) * 65 + n2 + 1];
            float2 hv = *reinterpret_cast<const float2*>(&hidden[(size_t)(row0 + r + 1) * 64 + n2]);
            float2 o;
            o.x = z0 * hv.x + (1.0f - z0) * hc0;
            o.y = z1 * hv.y + (1.0f - z1) * hc1;
            *reinterpret_cast<float2*>(&out[(size_t)(row0 + r + 1) * 64 + n2]) = o;
        }
    }
}

extern "C" void kernel_launch(void* const* d_in, const int* in_sizes, int n_in,
                              void* d_out, int out_size) {
    const float* x      = (const float*)d_in[0];   // [16,1024,2]
    const float* hidden = (const float*)d_in[1];   // [16,1024,64]
    const float* rnn_W  = (const float*)d_in[12];  // [6,198,64]
    const float* rnn_b  = (const float*)d_in[13];  // [6,64]
    float* out = (float*)d_out;                    // [16,1024,64]

    fold_kernel<<<(3 * KDIM * 64 + 255) / 256, 256>>>(rnn_W, rnn_b);

    int smem_bytes = SMEM_FLOATS * (int)sizeof(float);
    cudaFuncSetAttribute(dgcrm_main,
                         cudaFuncAttributeMaxDynamicSharedMemorySize, smem_bytes);
    dgcrm_main<<<NBLK, 256, smem_bytes>>>(x, hidden, out);
}

// round 15
// speedup vs baseline: 1.0590x; 1.0590x over previous
#include <cuda_runtime.h>
#include <cuda_bf16.h>

// DGCRM live path only (DGCN branch dead; GConv_RNN bug makes hops alpha*x):
//   Wz=F(W0)+F(W1), Wr=F(W2)+F(W3), Wh=F(W4)+F(W5),
//   F(Wi)=Wi[0:66]+0.05*(Wi[66:132]+Wi[132:198])
//   z=sig(inp@Wz+bz); r=sig(inp@Wr+br); hc=tanh([x,r*hid]@Wh+bh)
//   out=z*hid+(1-z)*hc.  Internal col order: 0..63 hid, 64..65 x.
//
// R2: f32x2 packed FMAs (rows paired), column-major input tile for LDS.64
// operand loads, MT=64 -> 256 CTAs for 2 CTAs/SM occupancy.

#define NROWS 16384
#define KDIM  66
#define MT    64
#define NBLK  (NROWS / MT)   // 256
#define MTP   66             // sInT row stride (floats), 264B: 8B-aligned, staggers banks

typedef unsigned long long u64;

__device__ float g_W[3 * KDIM * 64];   // [mat][c'][j], c' permuted (hid first)
__device__ float g_b[3 * 64];

__device__ __forceinline__ float sigmoidf_(float v) {
    return 1.0f / (1.0f + __expf(-v));
}
__device__ __forceinline__ float tanh_fast(float v) {
    // tanh(v) = 2*sigmoid(2v) - 1  (exact at 0, correct saturation)
    return fmaf(2.0f, 1.0f / (1.0f + __expf(-2.0f * v)), -1.0f);
}
__device__ __forceinline__ u64 fma2(u64 a, u64 b, u64 c) {
    u64 d; asm("fma.rn.f32x2 %0, %1, %2, %3;" : "=l"(d) : "l"(a), "l"(b), "l"(c));
    return d;
}
__device__ __forceinline__ u64 dup2(float x) {
    u64 d; unsigned xi = __float_as_uint(x);
    asm("mov.b64 %0, {%1, %1};" : "=l"(d) : "r"(xi));
    return d;
}
__device__ __forceinline__ float2 unpk(u64 v) {
    unsigned lo, hi;
    asm("mov.b64 {%0, %1}, %2;" : "=r"(lo), "=r"(hi) : "l"(v));
    return make_float2(__uint_as_float(lo), __uint_as_float(hi));
}

__global__ void fold_kernel(const float* __restrict__ rnn_W,
                            const float* __restrict__ rnn_b) {
    int idx = blockIdx.x * 256 + threadIdx.x;
    if (idx < 3 * KDIM * 64) {
        int j = idx & 63;
        int c = (idx >> 6) % KDIM;
        int m = idx / (KDIM * 64);
        int orig = (c < 64) ? (c + 2) : (c - 64);   // original concat order: x first
        float v = 0.0f;
        #pragma unroll
        for (int t = 0; t < 2; t++) {
            const float* Wi = rnn_W + (size_t)(2 * m + t) * 198 * 64;
            v += Wi[orig * 64 + j]
               + 0.05f * (Wi[(66 + orig) * 64 + j] + Wi[(132 + orig) * 64 + j]);
        }
        g_W[idx] = v;
    }
    if (blockIdx.x == 0 && threadIdx.x < 3 * 64) {
        int m = threadIdx.x >> 6, j = threadIdx.x & 63;
        g_b[threadIdx.x] = rnn_b[(2 * m) * 64 + j] + rnn_b[(2 * m + 1) * 64 + j];
    }
}

// smem (floats): sInT[66][66] col-major input; sW[66][128]; sZ[64][65]; sB[192]
#define S_IN  0
#define S_W   (KDIM * MTP)                 // 4356
#define S_Z   (S_W + KDIM * 128)           // 12804
#define S_B   (S_Z + 64 * 65)              // 16964
#define SMEM_FLOATS (S_B + 192)            // 17156 floats = 68624 B

__global__ __launch_bounds__(256)
void dgcrm_main(const float* __restrict__ x,
                const float* __restrict__ hidden,
                float* __restrict__ out) {
    extern __shared__ float sm[];
    float* sInT = sm + S_IN;
    float* sW   = sm + S_W;
    float* sZ   = sm + S_Z;
    float* sB   = sm + S_B;

    const int tid  = threadIdx.x;
    const int row0 = blockIdx.x * MT;

    // ---- prologue: stage inputs (transposed) + zr weights ----
    for (int i = tid; i < MT * 16; i += 256) {            // hidden -> sInT[c][m]
        int m = i >> 4, q = i & 15;
        float4 v = reinterpret_cast<const float4*>(hidden)[(size_t)(row0 + m) * 16 + q];
        sInT[(4 * q + 0) * MTP + m] = v.x;
        sInT[(4 * q + 1) * MTP + m] = v.y;
        sInT[(4 * q + 2) * MTP + m] = v.z;
        sInT[(4 * q + 3) * MTP + m] = v.w;
    }
    for (int i = tid; i < MT * 2; i += 256) {             // x -> sInT[64|65][m]
        int m = i >> 1, c = i & 1;
        sInT[(64 + c) * MTP + m] = x[(size_t)(row0 + m) * 2 + c];
    }
    for (int i = tid; i < KDIM * 32; i += 256) {          // sW[c][0..127] = [Wz|Wr]
        int c = i >> 5, q = i & 31;
        float4 v = (q < 16)
            ? reinterpret_cast<const float4*>(g_W)[(0 * KDIM + c) * 16 + q]
            : reinterpret_cast<const float4*>(g_W)[(1 * KDIM + c) * 16 + (q - 16)];
        *reinterpret_cast<float4*>(&sW[c * 128 + q * 4]) = v;
    }
    if (tid < 192) sB[tid] = g_b[tid];
    __syncthreads();

    const int tx = tid & 31, ty = tid >> 5;
    const int m0 = ty * 8;          // 8 rows (4 packed pairs)
    const int n1 = tx * 4;          // pass1: 4 cols of 128

    // ---- pass 1: [64x66] @ [66x128] -> z|r pre-activations (f32x2) ----
    u64 acc[4][4];
    #pragma unroll
    for (int p = 0; p < 4; p++)
        #pragma unroll
        for (int j = 0; j < 4; j++) acc[p][j] = 0ull;

    #pragma unroll 2
    for (int c = 0; c < KDIM; c++) {
        const float* aP = sInT + c * MTP + m0;
        u64 a0 = *reinterpret_cast<const u64*>(aP + 0);
        u64 a1 = *reinterpret_cast<const u64*>(aP + 2);
        u64 a2 = *reinterpret_cast<const u64*>(aP + 4);
        u64 a3 = *reinterpret_cast<const u64*>(aP + 6);
        float4 b4 = *reinterpret_cast<const float4*>(sW + c * 128 + n1);
        u64 b0 = dup2(b4.x), b1 = dup2(b4.y), b2 = dup2(b4.z), b3 = dup2(b4.w);
        acc[0][0] = fma2(a0, b0, acc[0][0]); acc[0][1] = fma2(a0, b1, acc[0][1]);
        acc[0][2] = fma2(a0, b2, acc[0][2]); acc[0][3] = fma2(a0, b3, acc[0][3]);
        acc[1][0] = fma2(a1, b0, acc[1][0]); acc[1][1] = fma2(a1, b1, acc[1][1]);
        acc[1][2] = fma2(a1, b2, acc[1][2]); acc[1][3] = fma2(a1, b3, acc[1][3]);
        acc[2][0] = fma2(a2, b0, acc[2][0]); acc[2][1] = fma2(a2, b1, acc[2][1]);
        acc[2][2] = fma2(a2, b2, acc[2][2]); acc[2][3] = fma2(a2, b3, acc[2][3]);
        acc[3][0] = fma2(a3, b0, acc[3][0]); acc[3][1] = fma2(a3, b1, acc[3][1]);
        acc[3][2] = fma2(a3, b2, acc[3][2]); acc[3][3] = fma2(a3, b3, acc[3][3]);
    }
    __syncthreads();   // all reads of sInT/sW done before overwrite

    // ---- epilogue 1: z -> sZ ; r -> sInT (in place r*hid) ----
    if (n1 < 64) {
        #pragma unroll
        for (int p = 0; p < 4; p++) {
            int r = m0 + 2 * p;
            #pragma unroll
            for (int j = 0; j < 4; j++) {
                int col = n1 + j;
                float2 v = unpk(acc[p][j]);
                sZ[r * 65 + col]       = sigmoidf_(v.x + sB[col]);
                sZ[(r + 1) * 65 + col] = sigmoidf_(v.y + sB[col]);
            }
        }
    } else {
        #pragma unroll
        for (int p = 0; p < 4; p++) {
            int r = m0 + 2 * p;
            #pragma unroll
            for (int j = 0; j < 4; j++) {
                int col = n1 - 64 + j;
                float2 v = unpk(acc[p][j]);
                float* q = sInT + col * MTP + r;     // unique writer per element
                q[0] *= sigmoidf_(v.x + sB[64 + col]);
                q[1] *= sigmoidf_(v.y + sB[64 + col]);
            }
        }
    }
    // overwrite sW cols 0..63 with Wh
    for (int i = tid; i < KDIM * 16; i += 256) {
        int c = i >> 4, q = i & 15;
        *reinterpret_cast<float4*>(&sW[c * 128 + q * 4]) =
            reinterpret_cast<const float4*>(g_W)[(2 * KDIM + c) * 16 + q];
    }
    __syncthreads();

    // ---- pass 2: [64x66](cand) @ [66x64] -> hc pre-activations ----
    const int n2 = tx * 2;
    u64 acc2[4][2];
    #pragma unroll
    for (int p = 0; p < 4; p++) { acc2[p][0] = 0ull; acc2[p][1] = 0ull; }

    #pragma unroll 2
    for (int c = 0; c < KDIM; c++) {
        const float* aP = sInT + c * MTP + m0;
        u64 a0 = *reinterpret_cast<const u64*>(aP + 0);
        u64 a1 = *reinterpret_cast<const u64*>(aP + 2);
        u64 a2 = *reinterpret_cast<const u64*>(aP + 4);
        u64 a3 = *reinterpret_cast<const u64*>(aP + 6);
        float2 b2v = *reinterpret_cast<const float2*>(sW + c * 128 + n2);
        u64 b0 = dup2(b2v.x), b1 = dup2(b2v.y);
        acc2[0][0] = fma2(a0, b0, acc2[0][0]); acc2[0][1] = fma2(a0, b1, acc2[0][1]);
        acc2[1][0] = fma2(a1, b0, acc2[1][0]); acc2[1][1] = fma2(a1, b1, acc2[1][1]);
        acc2[2][0] = fma2(a2, b0, acc2[2][0]); acc2[2][1] = fma2(a2, b1, acc2[2][1]);
        acc2[3][0] = fma2(a3, b0, acc2[3][0]); acc2[3][1] = fma2(a3, b1, acc2[3][1]);
    }

    // ---- epilogue 2: out = z*hid + (1-z)*tanh(hc) ----
    #pragma unroll
    for (int p = 0; p < 4; p++) {
        int r = m0 + 2 * p;
        float2 v0 = unpk(acc2[p][0]);   // col n2,   rows r / r+1
        float2 v1 = unpk(acc2[p][1]);   // col n2+1, rows r / r+1
        float bh0 = sB[128 + n2], bh1 = sB[128 + n2 + 1];
        // row r
        {
            float hc0 = tanh_fast(v0.x + bh0);
            float hc1 = tanh_fast(v1.x + bh1);
            float z0 = sZ[r * 65 + n2], z1 = sZ[r * 65 + n2 + 1];
            float2 hv = *reinterpret_cast<const float2*>(&hidden[(size_t)(row0 + r) * 64 + n2]);
            float2 o;
            o.x = z0 * hv.x + (1.0f - z0) * hc0;
            o.y = z1 * hv.y + (1.0f - z1) * hc1;
            *reinterpret_cast<float2*>(&out[(size_t)(row0 + r) * 64 + n2]) = o;
        }
        // row r+1
        {
            float hc0 = tanh_fast(v0.y + bh0);
            float hc1 = tanh_fast(v1.y + bh1);
            float z0 = sZ[(r + 1) * 65 + n2], z1 = sZ[(r + 1) * 65 + n2 + 1];
            float2 hv = *reinterpret_cast<const float2*>(&hidden[(size_t)(row0 + r + 1) * 64 + n2]);
            float2 o;
            o.x = z0 * hv.x + (1.0f - z0) * hc0;
            o.y = z1 * hv.y + (1.0f - z1) * hc1;
            *reinterpret_cast<float2*>(&out[(size_t)(row0 + r + 1) * 64 + n2]) = o;
        }
    }
}

extern "C" void kernel_launch(void* const* d_in, const int* in_sizes, int n_in,
                              void* d_out, int out_size) {
    const float* x      = (const float*)d_in[0];   // [16,1024,2]
    const float* hidden = (const float*)d_in[1];   // [16,1024,64]
    const float* rnn_W  = (const float*)d_in[12];  // [6,198,64]
    const float* rnn_b  = (const float*)d_in[13];  // [6,64]
    float* out = (float*)d_out;                    // [16,1024,64]

    fold_kernel<<<(3 * KDIM * 64 + 255) / 256, 256>>>(rnn_W, rnn_b);

    int smem_bytes = SMEM_FLOATS * (int)sizeof(float);
    cudaFuncSetAttribute(dgcrm_main,
                         cudaFuncAttributeMaxDynamicSharedMemorySize, smem_bytes);
    dgcrm_main<<<NBLK, 256, smem_bytes>>>(x, hidden, out);
}